// round 16
// baseline (speedup 1.0000x reference)
#include <cuda_runtime.h>
#include <cuda_fp16.h>
#include <cstdint>

// ---------------------------------------------------------------------------
// MultiShapeNet: h = sin(x@Wpre + bpre); 8 blocks of
//   h = gamma*h + beta;  r = sin(h@W0+b0); r = sin(r@W1+b1); h = 0.5*(h+r)
// N=262144, HIDDEN=128, fp32 in/out, rel_err < 1e-3.
//
// R16: occupancy push. One 512-thread CTA (16 warps, 4/SMSP — double R15's
// latency tolerance), 256 rows/CTA, M=16 rows/warp so per-thread state fits
// the 128-reg cap (fA 32 + acc 64 + misc). Single-term fp16 GEMM
// (r = fp16(A)*fp16(W), fp32 accum; measured 4.44e-4) and fp32 smem residual
// exactly as R15. smem layout unchanged. Kernel was latency-bound with every
// pipe <54% — more warps is the only remaining lever.
// ---------------------------------------------------------------------------

#define NLAY      16
#define WPAD      136           // halves per padded weight row
#define W_PITCH_B (WPAD*2)      // 272 bytes
#define WBUF_B    (128*W_PITCH_B)   // 34816 bytes per layer (fp16 W)
#define NBUF      2

// smem layout (bytes)
#define SM_W      0                          // 2 * 34816 = 69632
#define SM_F      (NBUF*WBUF_B)              // 69632 : 256 rows * 128 fp32 = 131072
#define SM_BB     (SM_F + 131072)            // 200704 : 16*128 fp32 = 8192
#define SM_WPRE   (SM_BB + 8192)             // 208896 : 512 fp32
#define SM_BPRE   (SM_WPRE + 2048)           // 210944 : 128 fp32
#define SM_MBAR   (SM_BPRE + 512)            // 211456 : 4 mbarriers
#define SMEM_TOTAL (SM_MBAR + 64)            // 211520

// weights scratch: [L][fp16 34816B], rows padded to 136 halves
__device__ unsigned char g_W[NLAY * WBUF_B];

// ---------------------------------------------------------------------------
// prep: W_blocks [16][128][128] fp32 -> fp16, padded rows
// ---------------------------------------------------------------------------
__global__ void msnet_prep_kernel(const float* __restrict__ Wb) {
    int t = blockIdx.x * blockDim.x + threadIdx.x;
    if (t < NLAY*128*128) {
        int L = t >> 14;
        int k = (t >> 7) & 127;
        int n = t & 127;
        __half* base = (__half*)(g_W + (size_t)L * WBUF_B);
        base[k*WPAD + n] = __float2half_rn(Wb[t]);
    }
    if (t < NLAY*128*8) {        // zero pad columns 128..135
        int L = t >> 10;
        int k = (t >> 3) & 127;
        int n = 128 + (t & 7);
        __half* base = (__half*)(g_W + (size_t)L * WBUF_B);
        base[k*WPAD + n] = __float2half_rn(0.f);
    }
}

// ---------------------------------------------------------------------------
// PTX helpers
// ---------------------------------------------------------------------------
#define LDSM_T4(r0,r1,r2,r3,addr) \
    asm volatile("ldmatrix.sync.aligned.m8n8.x4.trans.shared.b16 {%0,%1,%2,%3},[%4];\n" \
                 : "=r"(r0), "=r"(r1), "=r"(r2), "=r"(r3) : "r"(addr))

#define MMA16816(d0,d1,d2,d3,a0,a1,a2,a3,b0,b1) \
    asm volatile("mma.sync.aligned.m16n8k16.row.col.f32.f16.f16.f32 " \
                 "{%0,%1,%2,%3},{%4,%5,%6,%7},{%8,%9},{%0,%1,%2,%3};\n" \
                 : "+f"(d0), "+f"(d1), "+f"(d2), "+f"(d3) \
                 : "r"(a0), "r"(a1), "r"(a2), "r"(a3), "r"(b0), "r"(b1))

#define MBAR_INIT(mb, cnt) \
    asm volatile("mbarrier.init.shared.b64 [%0], %1;" :: "r"((uint32_t)(mb)), "r"((uint32_t)(cnt)) : "memory")
#define MBAR_EXPECT_TX(mb, b) \
    asm volatile("mbarrier.arrive.expect_tx.shared.b64 _, [%0], %1;" :: "r"((uint32_t)(mb)), "r"((uint32_t)(b)) : "memory")
#define MBAR_ARRIVE(mb) \
    asm volatile("mbarrier.arrive.shared.b64 _, [%0];" :: "r"((uint32_t)(mb)) : "memory")

__device__ __forceinline__ void mbar_wait(uint32_t mb, uint32_t parity) {
    asm volatile(
        "{.reg .pred P;\n"
        "W%=:\n"
        "mbarrier.try_wait.parity.acquire.cta.shared::cta.b64 P, [%0], %1, 0x989680;\n"
        "@P bra.uni D%=;\n"
        "bra.uni W%=;\n"
        "D%=:\n}"
        :: "r"(mb), "r"(parity) : "memory");
}

__device__ __forceinline__ void bulkcp(uint32_t dst, const void* src, uint32_t bytes, uint32_t mb) {
    unsigned long long g = (unsigned long long)__cvta_generic_to_global(src);
    asm volatile("cp.async.bulk.shared::cta.global.mbarrier::complete_tx::bytes [%0], [%1], %2, [%3];"
                 :: "r"(dst), "l"(g), "r"(bytes), "r"(mb) : "memory");
}

__device__ __forceinline__ void pfL2(const void* p) {
    asm volatile("prefetch.global.L2 [%0];" :: "l"(p));
}

// pack two fp32 into one half2 register
__device__ __forceinline__ uint32_t pack2(float a, float b) {
    __half2 h = __floats2half2_rn(a, b);
    return *reinterpret_cast<uint32_t*>(&h);
}

// Half-GEMM over n-tile-pairs NTP0..NTP0+3, all 8 K-chunks, M=16.
// Single-term: acc += fp16(A) * fp16(W), fp32 accumulate.
__device__ __forceinline__ void gemm_half(
    const uint32_t f[8][4], uint32_t wb, int NTP0, float (*acc)[4])
{
    #pragma unroll
    for (int kc = 0; kc < 8; kc++) {
        #pragma unroll
        for (int i = 0; i < 4; i++) {
            int ntp = NTP0 + i;
            uint32_t ah = wb + (uint32_t)(ntp*32 + kc*16*W_PITCH_B);
            uint32_t h0, h1, h2, h3;
            LDSM_T4(h0, h1, h2, h3, ah);
            int na = 2*i, nb = 2*i + 1;
            MMA16816(acc[na][0],acc[na][1],acc[na][2],acc[na][3],
                     f[kc][0],f[kc][1],f[kc][2],f[kc][3], h0,h1);
            MMA16816(acc[nb][0],acc[nb][1],acc[nb][2],acc[nb][3],
                     f[kc][0],f[kc][1],f[kc][2],f[kc][3], h2,h3);
        }
    }
}

// ---------------------------------------------------------------------------
// main fused kernel: 512 threads (16 warps), 256 rows per CTA, 16 rows/warp
// ---------------------------------------------------------------------------
__global__ void __launch_bounds__(512, 1) msnet_kernel(
    const float* __restrict__ x,
    const float* __restrict__ gammas,
    const float* __restrict__ betas,
    const float* __restrict__ W_pre,
    const float* __restrict__ b_pre,
    const float* __restrict__ b_blocks,
    float* __restrict__ out)
{
    extern __shared__ char smem[];
    uint32_t sb = (uint32_t)__cvta_generic_to_shared(smem);

    int tid  = threadIdx.x;          // 0..511
    int lane = tid & 31;
    int warp = tid >> 5;             // 0..15
    int gr = lane >> 2;              // group row 0..7
    int gc = (lane & 3) * 2;         // group col {0,2,4,6}

    size_t p0 = (size_t)blockIdx.x * 256 + warp * 16 + gr;
    size_t p1 = p0 + 8;

    uint32_t lane_off = (uint32_t)((lane & 15) * W_PITCH_B + (lane >> 4) * 16);

    uint32_t FULL0  = sb + SM_MBAR;
    uint32_t FULL1  = sb + SM_MBAR + 8;
    uint32_t EMPTY0 = sb + SM_MBAR + 16;
    uint32_t EMPTY1 = sb + SM_MBAR + 24;

    if (tid == 0) {
        MBAR_INIT(FULL0, 1);  MBAR_INIT(FULL1, 1);
        MBAR_INIT(EMPTY0, 512); MBAR_INIT(EMPTY1, 512);
    }

    float* sWpre = (float*)(smem + SM_WPRE);
    float* sBpre = (float*)(smem + SM_BPRE);
    float* sBB   = (float*)(smem + SM_BB);
    float2* sF2  = (float2*)(smem + SM_F);   // per-thread fp32 residual storage
    sWpre[tid] = W_pre[tid];                 // 512 floats exactly
    if (tid < 128) sBpre[tid] = b_pre[tid];
    for (int i = tid; i < NLAY*128; i += 512) sBB[i] = b_blocks[i];
    __syncthreads();   // mbar init + staging visible

    // kick TMA loads for layers 0,1
    if (tid == 0) {
        MBAR_EXPECT_TX(FULL0, WBUF_B);
        bulkcp(sb + SM_W, g_W, WBUF_B, FULL0);
        MBAR_EXPECT_TX(FULL1, WBUF_B);
        bulkcp(sb + SM_W + WBUF_B, g_W + WBUF_B, WBUF_B, FULL1);
    }

    uint32_t fA[8][4], fB[8][4];

    // --- pre-layer: h = sin(x @ Wpre + bpre), fused with FiLM(block 0) ---
    {
        float4 xva = ((const float4*)x)[p0];
        float4 xvb = ((const float4*)x)[p1];
        float xr0[4] = {xva.x, xva.y, xva.z, xva.w};
        float xr1[4] = {xvb.x, xvb.y, xvb.z, xvb.w};
        #pragma unroll
        for (int nt = 0; nt < 16; nt++) {
            int c = nt * 8 + gc;
            float t0 = sBpre[c], t1 = sBpre[c+1];
            float t2 = t0, t3 = t1;
            #pragma unroll
            for (int d = 0; d < 4; d++) {
                float w0 = sWpre[d*128 + c], w1 = sWpre[d*128 + c + 1];
                t0 = fmaf(xr0[d], w0, t0); t1 = fmaf(xr0[d], w1, t1);
                t2 = fmaf(xr1[d], w0, t2); t3 = fmaf(xr1[d], w1, t3);
            }
            t0 = __sinf(t0); t1 = __sinf(t1); t2 = __sinf(t2); t3 = __sinf(t3);
            float2 g0 = __ldcs((const float2*)(gammas + p0*1024 + c));
            float2 g1 = __ldcs((const float2*)(gammas + p1*1024 + c));
            float2 e0 = __ldcs((const float2*)(betas  + p0*1024 + c));
            float2 e1 = __ldcs((const float2*)(betas  + p1*1024 + c));
            float f0 = fmaf(g0.x, t0, e0.x), f1 = fmaf(g0.y, t1, e0.y);
            float f2 = fmaf(g1.x, t2, e1.x), f3 = fmaf(g1.y, t3, e1.y);
            int kc = nt >> 1, e = (nt & 1) * 2;
            fA[kc][e]   = pack2(f0, f1);
            fA[kc][e+1] = pack2(f2, f3);
            sF2[(nt*2)*512 + tid]   = make_float2(f0, f1);
            sF2[(nt*2+1)*512 + tid] = make_float2(f2, f3);
        }
    }

    #pragma unroll 1
    for (int blk = 0; blk < 8; blk++) {
        uint32_t up = (uint32_t)(blk & 1);

        // ============ even layer L=2blk : fA -> fB (r1) ============
        {
            int L = 2*blk;
            float acc[16][4];
            const float* bias = sBB + L * 128;
            #pragma unroll
            for (int nt = 0; nt < 16; nt++) {
                float2 b2 = *(const float2*)(bias + nt*8 + gc);
                acc[nt][0] = b2.x; acc[nt][1] = b2.y;
                acc[nt][2] = b2.x; acc[nt][3] = b2.y;
            }
            mbar_wait(FULL0, up);
            uint32_t wb = sb + SM_W + lane_off;

            gemm_half(fA, wb, 0, &acc[0]);
            #pragma unroll
            for (int nt = 0; nt < 8; nt++) {
                int kc = nt >> 1, e = (nt & 1) * 2;
                fB[kc][e]   = pack2(__sinf(acc[nt][0]), __sinf(acc[nt][1]));
                fB[kc][e+1] = pack2(__sinf(acc[nt][2]), __sinf(acc[nt][3]));
            }
            // L2 prefetch next block's FiLM rows (used end of next layer)
            if (blk < 7) {
                int co = (lane & 3) * 32;
                pfL2(gammas + p0*1024 + (size_t)(blk+1)*128 + co);
                pfL2(gammas + p1*1024 + (size_t)(blk+1)*128 + co);
                pfL2(betas  + p0*1024 + (size_t)(blk+1)*128 + co);
                pfL2(betas  + p1*1024 + (size_t)(blk+1)*128 + co);
            }
            gemm_half(fA, wb, 4, &acc[8]);
            MBAR_ARRIVE(EMPTY0);
            #pragma unroll
            for (int nt = 8; nt < 16; nt++) {
                int kc = nt >> 1, e = (nt & 1) * 2;
                fB[kc][e]   = pack2(__sinf(acc[nt][0]), __sinf(acc[nt][1]));
                fB[kc][e+1] = pack2(__sinf(acc[nt][2]), __sinf(acc[nt][3]));
            }
            if (tid == 0 && blk < 7) {
                mbar_wait(EMPTY0, up);
                MBAR_EXPECT_TX(FULL0, WBUF_B);
                bulkcp(sb + SM_W, g_W + (size_t)(L + 2) * WBUF_B, WBUF_B, FULL0);
            }
        }

        // ============ odd layer L=2blk+1 : fB -> fA, merge (+FiLM blk+1) ============
        {
            int L = 2*blk + 1;
            float acc[16][4];
            const float* bias = sBB + L * 128;
            #pragma unroll
            for (int nt = 0; nt < 16; nt++) {
                float2 b2 = *(const float2*)(bias + nt*8 + gc);
                acc[nt][0] = b2.x; acc[nt][1] = b2.y;
                acc[nt][2] = b2.x; acc[nt][3] = b2.y;
            }
            mbar_wait(FULL1, up);
            uint32_t wb = sb + SM_W + WBUF_B + lane_off;

            gemm_half(fB, wb, 0, &acc[0]);
            // merge+FiLM for n-tiles 0..7
            if (blk < 7) {
                #pragma unroll
                for (int nt = 0; nt < 8; nt++) {
                    int c = nt * 8 + gc;
                    float2 fv0 = sF2[(nt*2)*512 + tid];
                    float2 fv1 = sF2[(nt*2+1)*512 + tid];
                    float h0 = 0.5f * (fv0.x + __sinf(acc[nt][0]));
                    float h1 = 0.5f * (fv0.y + __sinf(acc[nt][1]));
                    float h2 = 0.5f * (fv1.x + __sinf(acc[nt][2]));
                    float h3 = 0.5f * (fv1.y + __sinf(acc[nt][3]));
                    float2 g0 = __ldcs((const float2*)(gammas + p0*1024 + (size_t)(blk+1)*128 + c));
                    float2 g1 = __ldcs((const float2*)(gammas + p1*1024 + (size_t)(blk+1)*128 + c));
                    float2 e0 = __ldcs((const float2*)(betas  + p0*1024 + (size_t)(blk+1)*128 + c));
                    float2 e1 = __ldcs((const float2*)(betas  + p1*1024 + (size_t)(blk+1)*128 + c));
                    float f0 = fmaf(g0.x, h0, e0.x), f1 = fmaf(g0.y, h1, e0.y);
                    float f2 = fmaf(g1.x, h2, e1.x), f3 = fmaf(g1.y, h3, e1.y);
                    int kc = nt >> 1, e = (nt & 1) * 2;
                    fA[kc][e]   = pack2(f0, f1);
                    fA[kc][e+1] = pack2(f2, f3);
                    sF2[(nt*2)*512 + tid]   = make_float2(f0, f1);
                    sF2[(nt*2+1)*512 + tid] = make_float2(f2, f3);
                }
            } else {
                #pragma unroll
                for (int nt = 0; nt < 8; nt++) {
                    int c = nt * 8 + gc;
                    float2 fv0 = sF2[(nt*2)*512 + tid];
                    float2 fv1 = sF2[(nt*2+1)*512 + tid];
                    *(float2*)&out[p0*128 + c] = make_float2(
                        0.5f * (fv0.x + __sinf(acc[nt][0])),
                        0.5f * (fv0.y + __sinf(acc[nt][1])));
                    *(float2*)&out[p1*128 + c] = make_float2(
                        0.5f * (fv1.x + __sinf(acc[nt][2])),
                        0.5f * (fv1.y + __sinf(acc[nt][3])));
                }
            }

            gemm_half(fB, wb, 4, &acc[8]);
            MBAR_ARRIVE(EMPTY1);
            // merge+FiLM for n-tiles 8..15
            if (blk < 7) {
                #pragma unroll
                for (int nt = 8; nt < 16; nt++) {
                    int c = nt * 8 + gc;
                    float2 fv0 = sF2[(nt*2)*512 + tid];
                    float2 fv1 = sF2[(nt*2+1)*512 + tid];
                    float h0 = 0.5f * (fv0.x + __sinf(acc[nt][0]));
                    float h1 = 0.5f * (fv0.y + __sinf(acc[nt][1]));
                    float h2 = 0.5f * (fv1.x + __sinf(acc[nt][2]));
                    float h3 = 0.5f * (fv1.y + __sinf(acc[nt][3]));
                    float2 g0 = __ldcs((const float2*)(gammas + p0*1024 + (size_t)(blk+1)*128 + c));
                    float2 g1 = __ldcs((const float2*)(gammas + p1*1024 + (size_t)(blk+1)*128 + c));
                    float2 e0 = __ldcs((const float2*)(betas  + p0*1024 + (size_t)(blk+1)*128 + c));
                    float2 e1 = __ldcs((const float2*)(betas  + p1*1024 + (size_t)(blk+1)*128 + c));
                    float f0 = fmaf(g0.x, h0, e0.x), f1 = fmaf(g0.y, h1, e0.y);
                    float f2 = fmaf(g1.x, h2, e1.x), f3 = fmaf(g1.y, h3, e1.y);
                    int kc = nt >> 1, e = (nt & 1) * 2;
                    fA[kc][e]   = pack2(f0, f1);
                    fA[kc][e+1] = pack2(f2, f3);
                    sF2[(nt*2)*512 + tid]   = make_float2(f0, f1);
                    sF2[(nt*2+1)*512 + tid] = make_float2(f2, f3);
                }
            } else {
                #pragma unroll
                for (int nt = 8; nt < 16; nt++) {
                    int c = nt * 8 + gc;
                    float2 fv0 = sF2[(nt*2)*512 + tid];
                    float2 fv1 = sF2[(nt*2+1)*512 + tid];
                    *(float2*)&out[p0*128 + c] = make_float2(
                        0.5f * (fv0.x + __sinf(acc[nt][0])),
                        0.5f * (fv0.y + __sinf(acc[nt][1])));
                    *(float2*)&out[p1*128 + c] = make_float2(
                        0.5f * (fv1.x + __sinf(acc[nt][2])),
                        0.5f * (fv1.y + __sinf(acc[nt][3])));
                }
            }

            if (tid == 0 && blk < 7) {
                mbar_wait(EMPTY1, up);
                MBAR_EXPECT_TX(FULL1, WBUF_B);
                bulkcp(sb + SM_W + WBUF_B, g_W + (size_t)(L + 2) * WBUF_B,
                       WBUF_B, FULL1);
            }
        }
    }
}

// ---------------------------------------------------------------------------
extern "C" void kernel_launch(void* const* d_in, const int* in_sizes, int n_in,
                              void* d_out, int out_size) {
    const float* x        = (const float*)d_in[0];
    const float* gammas   = (const float*)d_in[1];
    const float* betas    = (const float*)d_in[2];
    const float* W_pre    = (const float*)d_in[3];
    const float* b_pre    = (const float*)d_in[4];
    const float* W_blocks = (const float*)d_in[5];
    const float* b_blocks = (const float*)d_in[6];
    float* out = (float*)d_out;

    int N = in_sizes[0] / 4;   // 262144

    msnet_prep_kernel<<<(NLAY*128*128 + 255) / 256, 256>>>(W_blocks);

    cudaFuncSetAttribute(msnet_kernel,
                         cudaFuncAttributeMaxDynamicSharedMemorySize, SMEM_TOTAL);
    msnet_kernel<<<N / 256, 512, SMEM_TOTAL>>>(
        x, gammas, betas, W_pre, b_pre, b_blocks, out);
}